// round 1
// baseline (speedup 1.0000x reference)
#include <cuda_runtime.h>
#include <math_constants.h>
#include <cfloat>

#define NN 8192
#define DD 128
#define TOPK 32

// Scratch: per-feature top-K values and row indices (descending).
__device__ __align__(16) float g_topv[DD * TOPK];
__device__ __align__(16) int   g_topi[DD * TOPK];

// ---------------------------------------------------------------------------
// Kernel 1: per-feature top-K selection.
// One CTA (1024 threads) per feature d. Each thread holds 8 column values in
// registers; 32 iterations of block argmax, clearing the winner each time.
// ---------------------------------------------------------------------------
__global__ __launch_bounds__(1024) void topk_kernel(const float* __restrict__ x) {
    const int d   = blockIdx.x;
    const int tid = threadIdx.x;

    float v[8];
#pragma unroll
    for (int j = 0; j < 8; j++)
        v[j] = x[(size_t)(j * 1024 + tid) * DD + d];

    __shared__ float s_wv[32];
    __shared__ int   s_wi[32];
    __shared__ int   s_bi;

    for (int k = 0; k < TOPK; k++) {
        // thread-local argmax over 8 register slots
        float bv = v[0]; int bj = 0;
#pragma unroll
        for (int j = 1; j < 8; j++)
            if (v[j] > bv) { bv = v[j]; bj = j; }
        int bi = bj * 1024 + tid;  // global row index

        // warp reduce (val, idx)
#pragma unroll
        for (int o = 16; o > 0; o >>= 1) {
            float ov = __shfl_down_sync(0xffffffffu, bv, o);
            int   oi = __shfl_down_sync(0xffffffffu, bi, o);
            if (ov > bv) { bv = ov; bi = oi; }
        }
        if ((tid & 31) == 0) { s_wv[tid >> 5] = bv; s_wi[tid >> 5] = bi; }
        __syncthreads();

        if (tid < 32) {
            bv = s_wv[tid]; bi = s_wi[tid];
#pragma unroll
            for (int o = 16; o > 0; o >>= 1) {
                float ov = __shfl_down_sync(0xffffffffu, bv, o);
                int   oi = __shfl_down_sync(0xffffffffu, bi, o);
                if (ov > bv) { bv = ov; bi = oi; }
            }
            if (tid == 0) {
                s_bi = bi;
                g_topv[d * TOPK + k] = bv;
                g_topi[d * TOPK + k] = bi;
            }
        }
        __syncthreads();

        // owner of the winning row clears its register slot
        int wi = s_bi;
        if ((wi & 1023) == tid) v[wi >> 10] = -CUDART_INF_F;
        // no extra barrier needed: s_bi is only rewritten after the next
        // __syncthreads(), and only own registers are modified here.
    }
}

// ---------------------------------------------------------------------------
// Kernel 2: probe. One warp per row; each lane owns 4 features (d = f*32+lane).
// Walk the per-feature descending top-K list; the first entry that is a
// neighbor IS the masked max. Exact fallback (full-row masked scan) covers
// the all-K-miss and no-neighbor cases.
// ---------------------------------------------------------------------------
__global__ __launch_bounds__(512) void probe_kernel(const float* __restrict__ x,
                                                    const int*   __restrict__ adj,
                                                    float*       __restrict__ out) {
    __shared__ __align__(16) float s_topv[DD * TOPK];
    __shared__ __align__(16) int   s_topi[DD * TOPK];
    {
        const float4* gv = (const float4*)g_topv;
        const int4*   gi = (const int4*)g_topi;
        float4* sv = (float4*)s_topv;
        int4*   si = (int4*)s_topi;
        for (int t = threadIdx.x; t < DD * TOPK / 4; t += blockDim.x) {
            sv[t] = gv[t];
            si[t] = gi[t];
        }
    }
    __syncthreads();

    const int warp = threadIdx.x >> 5;
    const int lane = threadIdx.x & 31;
    const int row  = blockIdx.x * (blockDim.x >> 5) + warp;
    const int* __restrict__ arow = adj + (size_t)row * NN;

#pragma unroll
    for (int f = 0; f < 4; f++) {
        const int d    = f * 32 + lane;
        const int base = d * TOPK;
        float res = 0.0f;
        int k = 0;
        for (; k < TOPK; k++) {
            int c = s_topi[base + k];
            if (arow[c] != 0) { res = s_topv[base + k]; break; }
        }
        if (k == TOPK) {
            // Exact fallback: full masked row scan (also handles no-neighbor).
            float m = -FLT_MAX;
            int any = 0;
            for (int j = 0; j < NN; j++) {
                if (arow[j] != 0) { any = 1; m = fmaxf(m, x[(size_t)j * DD + d]); }
            }
            res = any ? m : 0.0f;
        }
        out[(size_t)row * DD + d] = res;
    }
}

extern "C" void kernel_launch(void* const* d_in, const int* in_sizes, int n_in,
                              void* d_out, int out_size) {
    const float* x   = (const float*)d_in[0];
    const int*   adj = (const int*)d_in[1];
    float*       out = (float*)d_out;

    topk_kernel<<<DD, 1024>>>(x);
    // 512 threads = 16 warps = 16 rows per block -> 512 blocks
    probe_kernel<<<NN / 16, 512>>>(x, adj, out);
}